// round 7
// baseline (speedup 1.0000x reference)
#include <cuda_runtime.h>

#define BB 256
#define NN 4096
#define DD 64
#define GATE_D 65
#define SPLITS 8
#define RPS (NN / SPLITS) /* 512 rows per split */

// Scratch (no device allocation allowed).
__device__ float g_partial[(size_t)BB * SPLITS * DD]; // unnormalized read partials
__device__ float g_zc[(size_t)BB * SPLITS * 2];       // {Z, conf_num} partials
__device__ int   g_count[BB];                         // arrival counters (self-resetting)

__device__ __forceinline__ float fsigmoid(float x) {
    return 1.0f / (1.0f + __expf(-x));
}

// --------------------------------------------------------------------------
// Single fused kernel. Per row n:
//   copy vmem->vout, sim = masked dot(vm, new_value), e = exp(sim)
//   (no max subtraction: sum of positives, fp32-safe for |sim| < 85),
//   copy kmem->kout, acc += e * kmem_row, Z += e, conf += e*sigmoid(sim*w+b).
// Per-(b,split) partials go to global scratch; the LAST block per b (counted
// via threadfence+atomicAdd) finalizes: normalize, gate, not_first mask,
// write read[], append new_key/new_value rows.
// 8 warps/block; each half-warp (16 lanes x float4) owns one row per stream.
// Touch-once bulk data uses streaming (.cs) loads/stores.
// --------------------------------------------------------------------------
__global__ __launch_bounds__(256) void k_main(
    const float* __restrict__ vmem, const float* __restrict__ kmem,
    const float* __restrict__ nkey, const float* __restrict__ nval,
    const float* __restrict__ gate,
    const float* __restrict__ wconf, const float* __restrict__ bconf,
    const int* __restrict__ iter_raw,
    float* __restrict__ vout, float* __restrict__ kout, float* __restrict__ rout)
{
    const int b = blockIdx.y, split = blockIdx.x;
    const int tid = threadIdx.x;
    const int w = tid >> 5, lane = tid & 31;
    const int half = lane >> 4, l16 = lane & 15;

    // Decode iteration dtype inline (JAX may demote int64 -> int32). If int64
    // (LE), all odd 32-bit words are zero high-words; if int32 they're random
    // values in [0,4096). Benign race on s_is32 (only ever set to 1).
    __shared__ int s_is32;
    if (tid == 0) s_is32 = 0;
    __syncthreads();
    for (int i = tid; i < BB / 2; i += 256)
        if (__ldg(iter_raw + 2 * i + 1) != 0) s_is32 = 1;
    __syncthreads();
    const int it = s_is32 ? __ldg(iter_raw + b) : __ldg(iter_raw + 2 * b);
    const float wc = wconf[0], bc = bconf[0];

    const float4 q = *(const float4*)(nval + (size_t)b * DD + 4 * l16);
    const float4* __restrict__ vsrc = (const float4*)(vmem + (size_t)b * NN * DD);
    const float4* __restrict__ ksrc = (const float4*)(kmem + (size_t)b * NN * DD);
    float4* __restrict__ vdst = (float4*)(vout + (size_t)b * (NN + 1) * DD);
    float4* __restrict__ kdst = (float4*)(kout + (size_t)b * (NN + 1) * DD);
    const int n0 = split * RPS;

    float4 acc = make_float4(0.f, 0.f, 0.f, 0.f);
    float zsum = 0.0f, csum = 0.0f;

    #pragma unroll 4
    for (int i = 0; i < RPS / 16; ++i) {       // 32 iterations, 2 rows/warp each
        const int n = n0 + (i * 8 + w) * 2 + half;
        const size_t idx = (size_t)n * (DD / 4) + l16;
        const float4 v = __ldcs(vsrc + idx);
        const float4 kr = __ldcs(ksrc + idx);
        __stcs(vdst + idx, v);
        __stcs(kdst + idx, kr);

        float p = v.x * q.x + v.y * q.y + v.z * q.z + v.w * q.w;
        p += __shfl_xor_sync(0xffffffffu, p, 8);
        p += __shfl_xor_sync(0xffffffffu, p, 4);
        p += __shfl_xor_sync(0xffffffffu, p, 2);
        p += __shfl_xor_sync(0xffffffffu, p, 1);
        const float sim = (n <= it) ? p : 0.0f;   // masked sim participates as 0
        const float e = __expf(sim);

        acc.x += e * kr.x; acc.y += e * kr.y;
        acc.z += e * kr.z; acc.w += e * kr.w;
        if (l16 == 0) {                            // one lane per row
            zsum += e;
            csum += e * fsigmoid(sim * wc + bc);
        }
    }

    // Block reduction: acc over (8 warps x 2 halves), z/c over the 16 row-lanes.
    __shared__ float4 sacc[8][32];
    __shared__ float szc[8][2][2];
    sacc[w][lane] = acc;
    if (l16 == 0) { szc[w][half][0] = zsum; szc[w][half][1] = csum; }
    __syncthreads();

    if (tid < 16) {
        float4 t = make_float4(0.f, 0.f, 0.f, 0.f);
        #pragma unroll
        for (int ww = 0; ww < 8; ++ww) {
            const float4 a = sacc[ww][tid];        // half 0
            const float4 c = sacc[ww][tid + 16];   // half 1 (same dims)
            t.x += a.x + c.x; t.y += a.y + c.y;
            t.z += a.z + c.z; t.w += a.w + c.w;
        }
        *(float4*)(&g_partial[((size_t)b * SPLITS + split) * DD + 4 * tid]) = t;
    } else if (tid == 32) {
        float z = 0.0f, c = 0.0f;
        #pragma unroll
        for (int ww = 0; ww < 8; ++ww) {
            z += szc[ww][0][0] + szc[ww][1][0];
            c += szc[ww][0][1] + szc[ww][1][1];
        }
        g_zc[((size_t)b * SPLITS + split) * 2 + 0] = z;
        g_zc[((size_t)b * SPLITS + split) * 2 + 1] = c;
    }

    // -------- last-block-per-b finalization --------
    __shared__ int s_last;
    __syncthreads();                  // partial writes done block-wide
    if (tid == 0) {
        __threadfence();              // publish partials device-wide
        s_last = (atomicAdd(&g_count[b], 1) == SPLITS - 1);
    }
    __syncthreads();
    if (!s_last) return;
    __threadfence();                  // see other blocks' partials

    const bool not_first = it > 1;
    const size_t app = (size_t)b * (NN + 1) * DD + (size_t)NN * DD;

    __shared__ float sinvZ, sconf;
    if (tid == 0) {
        g_count[b] = 0;               // reset for next graph replay
        float z = 0.0f, c = 0.0f;
        #pragma unroll
        for (int sp = 0; sp < SPLITS; ++sp) {
            z += g_zc[((size_t)b * SPLITS + sp) * 2 + 0];
            c += g_zc[((size_t)b * SPLITS + sp) * 2 + 1];
        }
        sinvZ = 1.0f / z;
        sconf = c;
    }
    __syncthreads();

    if (tid < 64) {
        float s = 0.0f;
        #pragma unroll
        for (int sp = 0; sp < SPLITS; ++sp)
            s += g_partial[((size_t)b * SPLITS + sp) * DD + tid];
        const float r = not_first
            ? s * sinvZ * fsigmoid(gate[(size_t)b * GATE_D + tid]) : 0.0f;
        rout[(size_t)b * GATE_D + tid] = r;
        kout[app + tid] = nkey[(size_t)b * DD + tid];
        if (tid == 0) {
            const float rc = not_first
                ? sconf * sinvZ * fsigmoid(gate[(size_t)b * GATE_D + DD]) : 0.0f;
            rout[(size_t)b * GATE_D + DD] = rc;
        }
    } else if (tid < 128) {
        const int d = tid - 64;
        vout[app + d] = nval[(size_t)b * DD + d];
    }
}

// --------------------------------------------------------------------------
extern "C" void kernel_launch(void* const* d_in, const int* in_sizes, int n_in,
                              void* d_out, int out_size)
{
    const float* nkey = (const float*)d_in[0];       // [B, KD]
    const float* nval = (const float*)d_in[1];       // [B, VD]
    const float* kmem = (const float*)d_in[2];       // [B, N, KD]
    const float* vmem = (const float*)d_in[3];       // [B, N, VD]
    const float* gate = (const float*)d_in[4];       // [B, KD+1]
    const float* wconf = (const float*)d_in[5];      // [1,1]
    const float* bconf = (const float*)d_in[6];      // [1]
    const int* iter_raw = (const int*)d_in[7];       // [B,1] int32 or int64

    float* out = (float*)d_out;
    float* kout = out;                                    // [B, N+1, KD]
    float* vout = out + (size_t)BB * (NN + 1) * DD;       // [B, N+1, VD]
    float* rout = out + 2 * (size_t)BB * (NN + 1) * DD;   // [B, KD+1]

    k_main<<<dim3(SPLITS, BB), 256>>>(vmem, kmem, nkey, nval, gate,
                                      wconf, bconf, iter_raw,
                                      vout, kout, rout);
}

// round 9
// speedup vs baseline: 1.0101x; 1.0101x over previous
#include <cuda_runtime.h>

#define BB 256
#define NN 4096
#define DD 64
#define GATE_D 65
#define SPLITS 8
#define RPS (NN / SPLITS) /* 512 rows per split */

// Scratch (no device allocation allowed).
__device__ float g_partial[(size_t)BB * SPLITS * DD]; // unnormalized read partials
__device__ float g_zc[(size_t)BB * SPLITS * 2];       // {Z, conf_num} partials
__device__ int   g_count[BB];                         // arrival counters (self-resetting)

__device__ __forceinline__ float fsigmoid(float x) {
    return 1.0f / (1.0f + __expf(-x));
}

// --------------------------------------------------------------------------
// Single fused kernel. Per row n:
//   copy vmem->vout, sim = masked dot(vm, new_value), e = exp(sim)
//   (no max subtraction: sum of positives, fp32-safe for |sim| < 85),
//   copy kmem->kout, acc += e * kmem_row, Z += e, conf += e*sigmoid(sim*w+b).
// Per-(b,split) partials go to global scratch; the LAST block per b (counted
// via threadfence+atomicAdd) finalizes: normalize, gate, not_first mask,
// write read[], append new_key/new_value rows.
// 8 warps/block; each half-warp (16 lanes x float4) owns one row per stream.
// Touch-once bulk data uses streaming (.cs) loads/stores.
// --------------------------------------------------------------------------
__global__ __launch_bounds__(256) void k_main(
    const float* __restrict__ vmem, const float* __restrict__ kmem,
    const float* __restrict__ nkey, const float* __restrict__ nval,
    const float* __restrict__ gate,
    const float* __restrict__ wconf, const float* __restrict__ bconf,
    const int* __restrict__ iter_raw,
    float* __restrict__ vout, float* __restrict__ kout, float* __restrict__ rout)
{
    const int b = blockIdx.y, split = blockIdx.x;
    const int tid = threadIdx.x;
    const int w = tid >> 5, lane = tid & 31;
    const int half = lane >> 4, l16 = lane & 15;

    // Decode iteration dtype inline (JAX may demote int64 -> int32). If int64
    // (LE), all odd 32-bit words are zero high-words; if int32 they're random
    // values in [0,4096). Benign race on s_is32 (only ever set to 1).
    __shared__ int s_is32;
    if (tid == 0) s_is32 = 0;
    __syncthreads();
    for (int i = tid; i < BB / 2; i += 256)
        if (__ldg(iter_raw + 2 * i + 1) != 0) s_is32 = 1;
    __syncthreads();
    const int it = s_is32 ? __ldg(iter_raw + b) : __ldg(iter_raw + 2 * b);
    const float wc = wconf[0], bc = bconf[0];

    const float4 q = *(const float4*)(nval + (size_t)b * DD + 4 * l16);
    const float4* __restrict__ vsrc = (const float4*)(vmem + (size_t)b * NN * DD);
    const float4* __restrict__ ksrc = (const float4*)(kmem + (size_t)b * NN * DD);
    float4* __restrict__ vdst = (float4*)(vout + (size_t)b * (NN + 1) * DD);
    float4* __restrict__ kdst = (float4*)(kout + (size_t)b * (NN + 1) * DD);
    const int n0 = split * RPS;

    float4 acc = make_float4(0.f, 0.f, 0.f, 0.f);
    float zsum = 0.0f, csum = 0.0f;

    #pragma unroll 4
    for (int i = 0; i < RPS / 16; ++i) {       // 32 iterations, 2 rows/warp each
        const int n = n0 + (i * 8 + w) * 2 + half;
        const size_t idx = (size_t)n * (DD / 4) + l16;
        const float4 v = __ldcs(vsrc + idx);
        const float4 kr = __ldcs(ksrc + idx);
        __stcs(vdst + idx, v);
        __stcs(kdst + idx, kr);

        float p = v.x * q.x + v.y * q.y + v.z * q.z + v.w * q.w;
        p += __shfl_xor_sync(0xffffffffu, p, 8);
        p += __shfl_xor_sync(0xffffffffu, p, 4);
        p += __shfl_xor_sync(0xffffffffu, p, 2);
        p += __shfl_xor_sync(0xffffffffu, p, 1);
        const float sim = (n <= it) ? p : 0.0f;   // masked sim participates as 0
        const float e = __expf(sim);

        acc.x += e * kr.x; acc.y += e * kr.y;
        acc.z += e * kr.z; acc.w += e * kr.w;
        if (l16 == 0) {                            // one lane per row
            zsum += e;
            csum += e * fsigmoid(sim * wc + bc);
        }
    }

    // Block reduction: acc over (8 warps x 2 halves), z/c over the 16 row-lanes.
    __shared__ float4 sacc[8][32];
    __shared__ float szc[8][2][2];
    sacc[w][lane] = acc;
    if (l16 == 0) { szc[w][half][0] = zsum; szc[w][half][1] = csum; }
    __syncthreads();

    if (tid < 16) {
        float4 t = make_float4(0.f, 0.f, 0.f, 0.f);
        #pragma unroll
        for (int ww = 0; ww < 8; ++ww) {
            const float4 a = sacc[ww][tid];        // half 0
            const float4 c = sacc[ww][tid + 16];   // half 1 (same dims)
            t.x += a.x + c.x; t.y += a.y + c.y;
            t.z += a.z + c.z; t.w += a.w + c.w;
        }
        *(float4*)(&g_partial[((size_t)b * SPLITS + split) * DD + 4 * tid]) = t;
    } else if (tid == 32) {
        float z = 0.0f, c = 0.0f;
        #pragma unroll
        for (int ww = 0; ww < 8; ++ww) {
            z += szc[ww][0][0] + szc[ww][1][0];
            c += szc[ww][0][1] + szc[ww][1][1];
        }
        g_zc[((size_t)b * SPLITS + split) * 2 + 0] = z;
        g_zc[((size_t)b * SPLITS + split) * 2 + 1] = c;
    }

    // -------- last-block-per-b finalization --------
    __shared__ int s_last;
    __syncthreads();                  // partial writes done block-wide
    if (tid == 0) {
        __threadfence();              // publish partials device-wide
        s_last = (atomicAdd(&g_count[b], 1) == SPLITS - 1);
    }
    __syncthreads();
    if (!s_last) return;
    __threadfence();                  // see other blocks' partials

    const bool not_first = it > 1;
    const size_t app = (size_t)b * (NN + 1) * DD + (size_t)NN * DD;

    __shared__ float sinvZ, sconf;
    if (tid == 0) {
        g_count[b] = 0;               // reset for next graph replay
        float z = 0.0f, c = 0.0f;
        #pragma unroll
        for (int sp = 0; sp < SPLITS; ++sp) {
            z += g_zc[((size_t)b * SPLITS + sp) * 2 + 0];
            c += g_zc[((size_t)b * SPLITS + sp) * 2 + 1];
        }
        sinvZ = 1.0f / z;
        sconf = c;
    }
    __syncthreads();

    if (tid < 64) {
        float s = 0.0f;
        #pragma unroll
        for (int sp = 0; sp < SPLITS; ++sp)
            s += g_partial[((size_t)b * SPLITS + sp) * DD + tid];
        const float r = not_first
            ? s * sinvZ * fsigmoid(gate[(size_t)b * GATE_D + tid]) : 0.0f;
        rout[(size_t)b * GATE_D + tid] = r;
        kout[app + tid] = nkey[(size_t)b * DD + tid];
        if (tid == 0) {
            const float rc = not_first
                ? sconf * sinvZ * fsigmoid(gate[(size_t)b * GATE_D + DD]) : 0.0f;
            rout[(size_t)b * GATE_D + DD] = rc;
        }
    } else if (tid < 128) {
        const int d = tid - 64;
        vout[app + d] = nval[(size_t)b * DD + d];
    }
}

// --------------------------------------------------------------------------
extern "C" void kernel_launch(void* const* d_in, const int* in_sizes, int n_in,
                              void* d_out, int out_size)
{
    const float* nkey = (const float*)d_in[0];       // [B, KD]
    const float* nval = (const float*)d_in[1];       // [B, VD]
    const float* kmem = (const float*)d_in[2];       // [B, N, KD]
    const float* vmem = (const float*)d_in[3];       // [B, N, VD]
    const float* gate = (const float*)d_in[4];       // [B, KD+1]
    const float* wconf = (const float*)d_in[5];      // [1,1]
    const float* bconf = (const float*)d_in[6];      // [1]
    const int* iter_raw = (const int*)d_in[7];       // [B,1] int32 or int64

    float* out = (float*)d_out;
    float* kout = out;                                    // [B, N+1, KD]
    float* vout = out + (size_t)BB * (NN + 1) * DD;       // [B, N+1, VD]
    float* rout = out + 2 * (size_t)BB * (NN + 1) * DD;   // [B, KD+1]

    k_main<<<dim3(SPLITS, BB), 256>>>(vmem, kmem, nkey, nval, gate,
                                      wconf, bconf, iter_raw,
                                      vout, kout, rout);
}

// round 10
// speedup vs baseline: 1.0141x; 1.0040x over previous
#include <cuda_runtime.h>

#define BB 256
#define NN 4096
#define DD 64
#define GATE_D 65
#define SPLITS 8
#define RPS (NN / SPLITS) /* 512 rows per split */

// Scratch (no device allocation allowed).
__device__ float g_partial[(size_t)BB * SPLITS * DD]; // unnormalized read partials
__device__ float g_zc[(size_t)BB * SPLITS * 2];       // {Z, conf_num} partials
__device__ int   g_count[BB];                         // arrival counters (self-resetting)

__device__ __forceinline__ float fsigmoid(float x) {
    return 1.0f / (1.0f + __expf(-x));
}

// --------------------------------------------------------------------------
// Single fused kernel. Per row n:
//   copy vmem->vout, sim = masked dot(vm, new_value), e = exp(sim)
//   (no max subtraction: sum of positives, fp32-safe for |sim| < 85),
//   copy kmem->kout, acc += e * kmem_row, Z += e, conf += e*sigmoid(sim*w+b).
// Per-(b,split) partials go to global scratch; the LAST block per b (counted
// via threadfence+atomicAdd) finalizes: normalize, gate, not_first mask,
// write read[], append new_key/new_value rows.
// 8 warps/block; each half-warp (16 lanes x float4) owns one row per stream.
// Touch-once bulk data uses streaming (.cs) loads/stores.
// --------------------------------------------------------------------------
__global__ __launch_bounds__(256) void k_main(
    const float* __restrict__ vmem, const float* __restrict__ kmem,
    const float* __restrict__ nkey, const float* __restrict__ nval,
    const float* __restrict__ gate,
    const float* __restrict__ wconf, const float* __restrict__ bconf,
    const int* __restrict__ iter_raw,
    float* __restrict__ vout, float* __restrict__ kout, float* __restrict__ rout)
{
    const int b = blockIdx.y, split = blockIdx.x;
    const int tid = threadIdx.x;
    const int w = tid >> 5, lane = tid & 31;
    const int half = lane >> 4, l16 = lane & 15;

    // Decode iteration dtype inline (JAX may demote int64 -> int32). If int64
    // (LE), all odd 32-bit words are zero high-words; if int32 they're random
    // values in [0,4096). Benign race on s_is32 (only ever set to 1).
    __shared__ int s_is32;
    if (tid == 0) s_is32 = 0;
    __syncthreads();
    for (int i = tid; i < BB / 2; i += 256)
        if (__ldg(iter_raw + 2 * i + 1) != 0) s_is32 = 1;
    __syncthreads();
    const int it = s_is32 ? __ldg(iter_raw + b) : __ldg(iter_raw + 2 * b);
    const float wc = wconf[0], bc = bconf[0];

    const float4 q = *(const float4*)(nval + (size_t)b * DD + 4 * l16);
    const float4* __restrict__ vsrc = (const float4*)(vmem + (size_t)b * NN * DD);
    const float4* __restrict__ ksrc = (const float4*)(kmem + (size_t)b * NN * DD);
    float4* __restrict__ vdst = (float4*)(vout + (size_t)b * (NN + 1) * DD);
    float4* __restrict__ kdst = (float4*)(kout + (size_t)b * (NN + 1) * DD);
    const int n0 = split * RPS;

    float4 acc = make_float4(0.f, 0.f, 0.f, 0.f);
    float zsum = 0.0f, csum = 0.0f;

    #pragma unroll 4
    for (int i = 0; i < RPS / 16; ++i) {       // 32 iterations, 2 rows/warp each
        const int n = n0 + (i * 8 + w) * 2 + half;
        const size_t idx = (size_t)n * (DD / 4) + l16;
        const float4 v = __ldcs(vsrc + idx);
        const float4 kr = __ldcs(ksrc + idx);
        __stcs(vdst + idx, v);
        __stcs(kdst + idx, kr);

        float p = v.x * q.x + v.y * q.y + v.z * q.z + v.w * q.w;
        p += __shfl_xor_sync(0xffffffffu, p, 8);
        p += __shfl_xor_sync(0xffffffffu, p, 4);
        p += __shfl_xor_sync(0xffffffffu, p, 2);
        p += __shfl_xor_sync(0xffffffffu, p, 1);
        const float sim = (n <= it) ? p : 0.0f;   // masked sim participates as 0
        const float e = __expf(sim);

        acc.x += e * kr.x; acc.y += e * kr.y;
        acc.z += e * kr.z; acc.w += e * kr.w;
        if (l16 == 0) {                            // one lane per row
            zsum += e;
            csum += e * fsigmoid(sim * wc + bc);
        }
    }

    // Block reduction: acc over (8 warps x 2 halves), z/c over the 16 row-lanes.
    __shared__ float4 sacc[8][32];
    __shared__ float szc[8][2][2];
    sacc[w][lane] = acc;
    if (l16 == 0) { szc[w][half][0] = zsum; szc[w][half][1] = csum; }
    __syncthreads();

    if (tid < 16) {
        float4 t = make_float4(0.f, 0.f, 0.f, 0.f);
        #pragma unroll
        for (int ww = 0; ww < 8; ++ww) {
            const float4 a = sacc[ww][tid];        // half 0
            const float4 c = sacc[ww][tid + 16];   // half 1 (same dims)
            t.x += a.x + c.x; t.y += a.y + c.y;
            t.z += a.z + c.z; t.w += a.w + c.w;
        }
        *(float4*)(&g_partial[((size_t)b * SPLITS + split) * DD + 4 * tid]) = t;
    } else if (tid == 32) {
        float z = 0.0f, c = 0.0f;
        #pragma unroll
        for (int ww = 0; ww < 8; ++ww) {
            z += szc[ww][0][0] + szc[ww][1][0];
            c += szc[ww][0][1] + szc[ww][1][1];
        }
        g_zc[((size_t)b * SPLITS + split) * 2 + 0] = z;
        g_zc[((size_t)b * SPLITS + split) * 2 + 1] = c;
    }

    // -------- last-block-per-b finalization --------
    __shared__ int s_last;
    __syncthreads();                  // partial writes done block-wide
    if (tid == 0) {
        __threadfence();              // publish partials device-wide
        s_last = (atomicAdd(&g_count[b], 1) == SPLITS - 1);
    }
    __syncthreads();
    if (!s_last) return;
    __threadfence();                  // see other blocks' partials

    const bool not_first = it > 1;
    const size_t app = (size_t)b * (NN + 1) * DD + (size_t)NN * DD;

    __shared__ float sinvZ, sconf;
    if (tid == 0) {
        g_count[b] = 0;               // reset for next graph replay
        float z = 0.0f, c = 0.0f;
        #pragma unroll
        for (int sp = 0; sp < SPLITS; ++sp) {
            z += g_zc[((size_t)b * SPLITS + sp) * 2 + 0];
            c += g_zc[((size_t)b * SPLITS + sp) * 2 + 1];
        }
        sinvZ = 1.0f / z;
        sconf = c;
    }
    __syncthreads();

    if (tid < 64) {
        float s = 0.0f;
        #pragma unroll
        for (int sp = 0; sp < SPLITS; ++sp)
            s += g_partial[((size_t)b * SPLITS + sp) * DD + tid];
        const float r = not_first
            ? s * sinvZ * fsigmoid(gate[(size_t)b * GATE_D + tid]) : 0.0f;
        rout[(size_t)b * GATE_D + tid] = r;
        kout[app + tid] = nkey[(size_t)b * DD + tid];
        if (tid == 0) {
            const float rc = not_first
                ? sconf * sinvZ * fsigmoid(gate[(size_t)b * GATE_D + DD]) : 0.0f;
            rout[(size_t)b * GATE_D + DD] = rc;
        }
    } else if (tid < 128) {
        const int d = tid - 64;
        vout[app + d] = nval[(size_t)b * DD + d];
    }
}

// --------------------------------------------------------------------------
extern "C" void kernel_launch(void* const* d_in, const int* in_sizes, int n_in,
                              void* d_out, int out_size)
{
    const float* nkey = (const float*)d_in[0];       // [B, KD]
    const float* nval = (const float*)d_in[1];       // [B, VD]
    const float* kmem = (const float*)d_in[2];       // [B, N, KD]
    const float* vmem = (const float*)d_in[3];       // [B, N, VD]
    const float* gate = (const float*)d_in[4];       // [B, KD+1]
    const float* wconf = (const float*)d_in[5];      // [1,1]
    const float* bconf = (const float*)d_in[6];      // [1]
    const int* iter_raw = (const int*)d_in[7];       // [B,1] int32 or int64

    float* out = (float*)d_out;
    float* kout = out;                                    // [B, N+1, KD]
    float* vout = out + (size_t)BB * (NN + 1) * DD;       // [B, N+1, VD]
    float* rout = out + 2 * (size_t)BB * (NN + 1) * DD;   // [B, KD+1]

    k_main<<<dim3(SPLITS, BB), 256>>>(vmem, kmem, nkey, nval, gate,
                                      wconf, bconf, iter_raw,
                                      vout, kout, rout);
}